// round 1
// baseline (speedup 1.0000x reference)
#include <cuda_runtime.h>

#define Dq 128
#define EB 32
#define MAXN 50000

// Scratch (device globals — no runtime allocation allowed)
__device__ float g_agg[(size_t)MAXN * Dq];   // per-node edge_feat segment sum
__device__ float g_aggc[(size_t)MAXN * 4];   // per-node [sum_x,sum_y,sum_z,count]
__device__ int   g_is64;                     // edge_index dtype flag

__device__ __forceinline__ float silu_f(float x) {
    return x * (1.0f / (1.0f + __expf(-x)));
}

// Detect whether edge_index is int64 (all high 32-bit words zero) or int32.
__global__ void detect_kernel(const int* __restrict__ ei32) {
    if (threadIdx.x == 0 && blockIdx.x == 0) {
        int acc = 0;
        #pragma unroll
        for (int k = 0; k < 128; k++) acc |= ei32[2 * k + 1];
        g_is64 = (acc == 0) ? 1 : 0;
    }
}

__global__ void zero_kernel(int Nn) {
    int stride = gridDim.x * blockDim.x;
    for (int i = blockIdx.x * blockDim.x + threadIdx.x; i < Nn * Dq; i += stride)
        g_agg[i] = 0.f;
    for (int i = blockIdx.x * blockDim.x + threadIdx.x; i < Nn * 4; i += stride)
        g_aggc[i] = 0.f;
}

// Edge kernel: one block = 32 edges, 128 threads (thread = output feature).
// Fuses: radial, edge MLP (2 layers + SiLU), attention gate, coord MLP,
// clipped trans + scatter, edge_feat scatter + output.
__global__ __launch_bounds__(128) void edge_kernel(
    const float* __restrict__ h, const void* __restrict__ ei,
    const float* __restrict__ coord,
    const float* __restrict__ We1, const float* __restrict__ be1,
    const float* __restrict__ We2, const float* __restrict__ be2,
    const float* __restrict__ Watt, const float* __restrict__ batt,
    const float* __restrict__ Wc1, const float* __restrict__ bc1,
    const float* __restrict__ Wc2,
    float* __restrict__ ef_out, int E)
{
    __shared__ float s_buf[EB][260];   // [e][0:257] input, regions reused per stage
    __shared__ float s_cd[EB][3];
    __shared__ float s_sc[EB];         // att, then cw
    __shared__ int s_row[EB], s_col[EB];

    const int tid = threadIdx.x;
    const int e0 = blockIdx.x * EB;

    if (tid < EB) {
        int e = e0 + tid;
        int r = 0, c = 0;
        if (e < E) {
            if (g_is64) {
                const long long* p = (const long long*)ei;
                r = (int)p[e]; c = (int)p[E + e];
            } else {
                const int* p = (const int*)ei;
                r = p[e]; c = p[E + e];
            }
        }
        s_row[tid] = r; s_col[tid] = c;
        float dx = coord[r * 3 + 0] - coord[c * 3 + 0];
        float dy = coord[r * 3 + 1] - coord[c * 3 + 1];
        float dz = coord[r * 3 + 2] - coord[c * 3 + 2];
        s_cd[tid][0] = dx; s_cd[tid][1] = dy; s_cd[tid][2] = dz;
        s_buf[tid][256] = dx * dx + dy * dy + dz * dz;
    }
    __syncthreads();

    // Gather h[row] -> cols [0,128), h[col] -> cols [128,256). Coalesced float4.
    for (int idx = tid; idx < EB * 32; idx += 128) {
        int e = idx >> 5;
        int j = (idx & 31) << 2;
        *(float4*)&s_buf[e][j]       = *(const float4*)&h[(size_t)s_row[e] * Dq + j];
        *(float4*)&s_buf[e][128 + j] = *(const float4*)&h[(size_t)s_col[e] * Dq + j];
    }
    __syncthreads();

    // ---- GEMM1: [EB,257] @ We1[257,128] ----
    float acc[EB];
    #pragma unroll
    for (int e = 0; e < EB; e++) acc[e] = 0.f;
    for (int i = 0; i < 256; i += 4) {
        float w0 = We1[(i + 0) * Dq + tid];
        float w1 = We1[(i + 1) * Dq + tid];
        float w2 = We1[(i + 2) * Dq + tid];
        float w3 = We1[(i + 3) * Dq + tid];
        #pragma unroll
        for (int e = 0; e < EB; e++) {
            float4 v = *(const float4*)&s_buf[e][i];
            acc[e] = fmaf(v.x, w0, acc[e]);
            acc[e] = fmaf(v.y, w1, acc[e]);
            acc[e] = fmaf(v.z, w2, acc[e]);
            acc[e] = fmaf(v.w, w3, acc[e]);
        }
    }
    {
        float w = We1[256 * Dq + tid];
        float b = be1[tid];
        #pragma unroll
        for (int e = 0; e < EB; e++)
            acc[e] = silu_f(fmaf(s_buf[e][256], w, acc[e]) + b);
    }
    __syncthreads();                       // GEMM1 readers done before overwrite
    #pragma unroll
    for (int e = 0; e < EB; e++) s_buf[e][tid] = acc[e];   // mid -> cols [0,128)
    __syncthreads();

    // ---- GEMM2: mid @ We2[128,128] ----
    #pragma unroll
    for (int e = 0; e < EB; e++) acc[e] = 0.f;
    for (int i = 0; i < 128; i += 4) {
        float w0 = We2[(i + 0) * Dq + tid];
        float w1 = We2[(i + 1) * Dq + tid];
        float w2 = We2[(i + 2) * Dq + tid];
        float w3 = We2[(i + 3) * Dq + tid];
        #pragma unroll
        for (int e = 0; e < EB; e++) {
            float4 v = *(const float4*)&s_buf[e][i];
            acc[e] = fmaf(v.x, w0, acc[e]);
            acc[e] = fmaf(v.y, w1, acc[e]);
            acc[e] = fmaf(v.z, w2, acc[e]);
            acc[e] = fmaf(v.w, w3, acc[e]);
        }
    }
    {
        float b = be2[tid];
        #pragma unroll
        for (int e = 0; e < EB; e++) acc[e] = silu_f(acc[e] + b);
    }
    // store unscaled ef -> cols [128,256) (disjoint from GEMM2 read region)
    #pragma unroll
    for (int e = 0; e < EB; e++) s_buf[e][128 + tid] = acc[e];
    __syncthreads();

    // ---- attention: sigmoid(ef @ Watt + batt), warp-per-8-edges reduce ----
    const int wrp = tid >> 5, lane = tid & 31;
    {
        float a0 = Watt[lane], a1 = Watt[lane + 32], a2 = Watt[lane + 64], a3 = Watt[lane + 96];
        float bb = batt[0];
        #pragma unroll
        for (int k = 0; k < EB / 4; k++) {
            int e = wrp * (EB / 4) + k;
            float p = s_buf[e][128 + lane] * a0 + s_buf[e][160 + lane] * a1
                    + s_buf[e][192 + lane] * a2 + s_buf[e][224 + lane] * a3;
            #pragma unroll
            for (int off = 16; off > 0; off >>= 1)
                p += __shfl_xor_sync(0xffffffffu, p, off);
            if (lane == 0) s_sc[e] = 1.f / (1.f + __expf(-(p + bb)));
        }
    }
    __syncthreads();
    #pragma unroll
    for (int e = 0; e < EB; e++) {
        acc[e] *= s_sc[e];               // acc = final edge_feat
        s_buf[e][128 + tid] = acc[e];    // scaled ef for GEMM3
    }
    __syncthreads();

    // ---- GEMM3: ef @ Wc1[128,128], SiLU ----
    float acc2[EB];
    #pragma unroll
    for (int e = 0; e < EB; e++) acc2[e] = 0.f;
    for (int i = 0; i < 128; i += 4) {
        float w0 = Wc1[(i + 0) * Dq + tid];
        float w1 = Wc1[(i + 1) * Dq + tid];
        float w2 = Wc1[(i + 2) * Dq + tid];
        float w3 = Wc1[(i + 3) * Dq + tid];
        #pragma unroll
        for (int e = 0; e < EB; e++) {
            float4 v = *(const float4*)&s_buf[e][128 + i];
            acc2[e] = fmaf(v.x, w0, acc2[e]);
            acc2[e] = fmaf(v.y, w1, acc2[e]);
            acc2[e] = fmaf(v.z, w2, acc2[e]);
            acc2[e] = fmaf(v.w, w3, acc2[e]);
        }
    }
    {
        float b = bc1[tid];
        #pragma unroll
        for (int e = 0; e < EB; e++) acc2[e] = silu_f(acc2[e] + b);
    }
    #pragma unroll
    for (int e = 0; e < EB; e++) s_buf[e][tid] = acc2[e];   // c1 -> cols [0,128)
    __syncthreads();

    // ---- cw = c1 @ Wc2 ----
    {
        float a0 = Wc2[lane], a1 = Wc2[lane + 32], a2 = Wc2[lane + 64], a3 = Wc2[lane + 96];
        #pragma unroll
        for (int k = 0; k < EB / 4; k++) {
            int e = wrp * (EB / 4) + k;
            float p = s_buf[e][lane] * a0 + s_buf[e][32 + lane] * a1
                    + s_buf[e][64 + lane] * a2 + s_buf[e][96 + lane] * a3;
            #pragma unroll
            for (int off = 16; off > 0; off >>= 1)
                p += __shfl_xor_sync(0xffffffffu, p, off);
            if (lane == 0) s_sc[e] = p;
        }
    }
    __syncthreads();

    // ---- outputs: edge_feat (global) + feature scatter-add ----
    #pragma unroll
    for (int e = 0; e < EB; e++) {
        if (e0 + e < E) {
            float v = acc[e];
            ef_out[(size_t)(e0 + e) * Dq + tid] = v;
            atomicAdd(&g_agg[(size_t)s_row[e] * Dq + tid], v);
        }
    }
    // ---- clipped trans scatter + degree count ----
    if (tid < EB && (e0 + tid) < E) {
        float cw = s_sc[tid];
        int r = s_row[tid];
        float t0 = fminf(10.f, fmaxf(-10.f, s_cd[tid][0] * cw));
        float t1 = fminf(10.f, fmaxf(-10.f, s_cd[tid][1] * cw));
        float t2 = fminf(10.f, fmaxf(-10.f, s_cd[tid][2] * cw));
        atomicAdd(&g_aggc[r * 4 + 0], t0);
        atomicAdd(&g_aggc[r * 4 + 1], t1);
        atomicAdd(&g_aggc[r * 4 + 2], t2);
        atomicAdd(&g_aggc[r * 4 + 3], 1.0f);
    }
}

// Node kernel: one block = 32 nodes. Fuses coord mean/clip/update and node MLP.
__global__ __launch_bounds__(128) void node_kernel(
    const float* __restrict__ h, const float* __restrict__ coord,
    const float* __restrict__ Wn1, const float* __restrict__ bn1,
    const float* __restrict__ Wn2, const float* __restrict__ bn2,
    float* __restrict__ h_out, float* __restrict__ coord_out, int Nn)
{
    __shared__ float s_buf[EB][260];
    const int tid = threadIdx.x;
    const int n0 = blockIdx.x * EB;

    for (int idx = tid; idx < EB * 32; idx += 128) {
        int e = idx >> 5;
        int j = (idx & 31) << 2;
        int n = n0 + e; if (n >= Nn) n = 0;
        *(float4*)&s_buf[e][j]       = *(const float4*)&h[(size_t)n * Dq + j];
        *(float4*)&s_buf[e][128 + j] = *(const float4*)&g_agg[(size_t)n * Dq + j];
    }
    __syncthreads();

    // GEMM1: [h,agg](256) @ Wn1[256,128]
    float acc[EB];
    #pragma unroll
    for (int e = 0; e < EB; e++) acc[e] = 0.f;
    for (int i = 0; i < 256; i += 4) {
        float w0 = Wn1[(i + 0) * Dq + tid];
        float w1 = Wn1[(i + 1) * Dq + tid];
        float w2 = Wn1[(i + 2) * Dq + tid];
        float w3 = Wn1[(i + 3) * Dq + tid];
        #pragma unroll
        for (int e = 0; e < EB; e++) {
            float4 v = *(const float4*)&s_buf[e][i];
            acc[e] = fmaf(v.x, w0, acc[e]);
            acc[e] = fmaf(v.y, w1, acc[e]);
            acc[e] = fmaf(v.z, w2, acc[e]);
            acc[e] = fmaf(v.w, w3, acc[e]);
        }
    }
    {
        float b = bn1[tid];
        #pragma unroll
        for (int e = 0; e < EB; e++) acc[e] = silu_f(acc[e] + b);
    }
    __syncthreads();
    #pragma unroll
    for (int e = 0; e < EB; e++) s_buf[e][128 + tid] = acc[e];  // mid; keep h in [0,128)
    __syncthreads();

    // GEMM2: mid @ Wn2[128,128] + bn2 + h (residual)
    float acc2[EB];
    #pragma unroll
    for (int e = 0; e < EB; e++) acc2[e] = 0.f;
    for (int i = 0; i < 128; i += 4) {
        float w0 = Wn2[(i + 0) * Dq + tid];
        float w1 = Wn2[(i + 1) * Dq + tid];
        float w2 = Wn2[(i + 2) * Dq + tid];
        float w3 = Wn2[(i + 3) * Dq + tid];
        #pragma unroll
        for (int e = 0; e < EB; e++) {
            float4 v = *(const float4*)&s_buf[e][128 + i];
            acc2[e] = fmaf(v.x, w0, acc2[e]);
            acc2[e] = fmaf(v.y, w1, acc2[e]);
            acc2[e] = fmaf(v.z, w2, acc2[e]);
            acc2[e] = fmaf(v.w, w3, acc2[e]);
        }
    }
    {
        float b = bn2[tid];
        #pragma unroll
        for (int e = 0; e < EB; e++) {
            int n = n0 + e;
            if (n < Nn)
                h_out[(size_t)n * Dq + tid] = s_buf[e][tid] + acc2[e] + b;
        }
    }

    // coord update: mean with clipped count, clip, residual
    if (tid < EB) {
        int n = n0 + tid;
        if (n < Nn) {
            float cnt = fmaxf(g_aggc[n * 4 + 3], 1.f);
            #pragma unroll
            for (int d = 0; d < 3; d++) {
                float m = g_aggc[n * 4 + d] / cnt;
                m = fminf(10.f, fmaxf(-10.f, m));
                coord_out[n * 3 + d] = coord[n * 3 + d] + m;
            }
        }
    }
}

extern "C" void kernel_launch(void* const* d_in, const int* in_sizes, int n_in,
                              void* d_out, int out_size)
{
    const float* h     = (const float*)d_in[0];
    const void*  ei    = d_in[1];
    const float* coord = (const float*)d_in[2];
    const float* We1 = (const float*)d_in[3];  const float* be1 = (const float*)d_in[4];
    const float* We2 = (const float*)d_in[5];  const float* be2 = (const float*)d_in[6];
    const float* Watt= (const float*)d_in[7];  const float* batt= (const float*)d_in[8];
    const float* Wc1 = (const float*)d_in[9];  const float* bc1 = (const float*)d_in[10];
    const float* Wc2 = (const float*)d_in[11];
    const float* Wn1 = (const float*)d_in[12]; const float* bn1 = (const float*)d_in[13];
    const float* Wn2 = (const float*)d_in[14]; const float* bn2 = (const float*)d_in[15];

    int Nn = in_sizes[0] / Dq;
    int E  = in_sizes[1] / 2;

    float* out       = (float*)d_out;
    float* h_out     = out;                              // [N,128]
    float* coord_out = out + (size_t)Nn * Dq;            // [N,3]
    float* ef_out    = coord_out + (size_t)Nn * 3;       // [E,128]

    detect_kernel<<<1, 32>>>((const int*)ei);
    zero_kernel<<<1024, 256>>>(Nn);
    edge_kernel<<<(E + EB - 1) / EB, 128>>>(h, ei, coord,
                                            We1, be1, We2, be2, Watt, batt,
                                            Wc1, bc1, Wc2, ef_out, E);
    node_kernel<<<(Nn + EB - 1) / EB, 128>>>(h, coord, Wn1, bn1, Wn2, bn2,
                                             h_out, coord_out, Nn);
}